// round 1
// baseline (speedup 1.0000x reference)
#include <cuda_runtime.h>

// ---------------------------------------------------------------------------
// InformerStandard: B=8, P=16, L=1024, D=1024, H=16(dk=64), HZN=96, FF=32, 2 layers
// All fp32. Scratch in __device__ globals (no allocations).
// ---------------------------------------------------------------------------

#define B_  8
#define L_  1024
#define D_  1024
#define H_  16
#define DK_ 64
#define FF_ 32
#define U_  6
#define HZN_ 96
#define NROWS (B_*L_)   // 8192

__device__ float g_h[B_*L_*D_];       // 32 MB
__device__ float g_Q[B_*L_*D_];
__device__ float g_K[B_*L_*D_];
__device__ float g_V[B_*L_*D_];
__device__ float g_rowmax[B_*H_*L_];
__device__ int   g_top[B_*H_*U_];
__device__ float g_ctx[B_*H_*U_*DK_];
__device__ float g_mean[B_*D_];

#define DI __device__ __forceinline__

DI float bredSum(float v, float* red) {
    int tid = threadIdx.x;
    red[tid] = v; __syncthreads();
    #pragma unroll
    for (int off = 128; off > 0; off >>= 1) {
        if (tid < off) red[tid] += red[tid + off];
        __syncthreads();
    }
    float r = red[0]; __syncthreads(); return r;
}

DI float bredMax(float v, float* red) {
    int tid = threadIdx.x;
    red[tid] = v; __syncthreads();
    #pragma unroll
    for (int off = 128; off > 0; off >>= 1) {
        if (tid < off) red[tid] = fmaxf(red[tid], red[tid + off]);
        __syncthreads();
    }
    float r = red[0]; __syncthreads(); return r;
}

// ---------------------------------------------------------------------------
// Embed + positional encoding:
// h[b, d, l] = sum_p x[b,p,l]*emb_W[p,d] + emb_b[d] + pe(pos=d, dim=l)
// ---------------------------------------------------------------------------
__global__ void embed_kernel(const float* __restrict__ x,
                             const float* __restrict__ emb_W,
                             const float* __restrict__ emb_b) {
    int l = blockIdx.x * 256 + threadIdx.x;
    int d = blockIdx.y;
    int b = blockIdx.z;
    float acc = emb_b[d];
    #pragma unroll
    for (int p = 0; p < 16; p++)
        acc = fmaf(x[(b*16 + p)*L_ + l], emb_W[p*D_ + d], acc);
    const float C = -0.0089944730195f;          // -log(10000)/1024
    float div = expf((float)(l & ~1) * C);
    float arg = (float)d * div;
    float pe = (l & 1) ? cosf(arg) : sinf(arg);
    g_h[(b*L_ + d)*D_ + l] = acc + pe;          // note: (seq=d, feat=l)
}

// ---------------------------------------------------------------------------
// SGEMM: C[M,N] = A[M,K] @ B[K,N] + bias[N].  BM=BN=128, BK=8, 256 thr, 8x8/thr
// ---------------------------------------------------------------------------
__global__ void __launch_bounds__(256)
sgemm_bias(const float* __restrict__ A, const float* __restrict__ Bm,
           const float* __restrict__ bias, float* __restrict__ C,
           int M, int N, int K) {
    __shared__ float As[8][128];
    __shared__ float Bs[8][128];
    int tid = threadIdx.x;
    int tRow = tid / 16, tCol = tid % 16;
    int aRow = tid >> 1, aCol = (tid & 1) * 4;
    int bRow = tid >> 5, bCol = (tid & 31) * 4;
    const float* Ab = A + (size_t)blockIdx.y * 128 * K;
    const float* Bb = Bm + blockIdx.x * 128;
    float acc[8][8];
    #pragma unroll
    for (int i = 0; i < 8; i++)
        #pragma unroll
        for (int j = 0; j < 8; j++) acc[i][j] = 0.f;

    for (int k0 = 0; k0 < K; k0 += 8) {
        float4 av = *(const float4*)(Ab + (size_t)aRow * K + k0 + aCol);
        As[aCol+0][aRow] = av.x; As[aCol+1][aRow] = av.y;
        As[aCol+2][aRow] = av.z; As[aCol+3][aRow] = av.w;
        *(float4*)(&Bs[bRow][bCol]) = *(const float4*)(Bb + (size_t)(k0 + bRow) * N + bCol);
        __syncthreads();
        #pragma unroll
        for (int k = 0; k < 8; k++) {
            float4 a0 = *(float4*)&As[k][tRow*8];
            float4 a1 = *(float4*)&As[k][tRow*8+4];
            float4 b0 = *(float4*)&Bs[k][tCol*8];
            float4 b1 = *(float4*)&Bs[k][tCol*8+4];
            float ra[8] = {a0.x,a0.y,a0.z,a0.w,a1.x,a1.y,a1.z,a1.w};
            float rb[8] = {b0.x,b0.y,b0.z,b0.w,b1.x,b1.y,b1.z,b1.w};
            #pragma unroll
            for (int i = 0; i < 8; i++)
                #pragma unroll
                for (int j = 0; j < 8; j++)
                    acc[i][j] = fmaf(ra[i], rb[j], acc[i][j]);
        }
        __syncthreads();
    }
    float* Cb = C + (size_t)blockIdx.y*128*N + blockIdx.x*128;
    #pragma unroll
    for (int i = 0; i < 8; i++) {
        int r = tRow*8 + i;
        #pragma unroll
        for (int j = 0; j < 8; j += 4) {
            int c = tCol*8 + j;
            float4 bv = *(const float4*)(bias + blockIdx.x*128 + c);
            float4 o = { acc[i][j]+bv.x, acc[i][j+1]+bv.y, acc[i][j+2]+bv.z, acc[i][j+3]+bv.w };
            *(float4*)(Cb + (size_t)r*N + c) = o;
        }
    }
}

// ---------------------------------------------------------------------------
// Fused QK^T row-max: rowmax[b,h,l] = max_m Q[b,l,h,:].K[b,m,h,:]
// Block: 64 l-rows, loops all 16 m-tiles of 64. 256 threads, 4x4 micro-tile.
// smem pitch 68 floats (16B aligned, conflict-free for row-stride reads).
// ---------------------------------------------------------------------------
__global__ void __launch_bounds__(256)
scores_rowmax_kernel() {
    __shared__ float Qs[64*68];
    __shared__ float Ks[64*68];
    __shared__ float red[64*16];
    int lt = blockIdx.x, hh = blockIdx.y, b = blockIdx.z;
    int tid = threadIdx.x;
    int tx = tid & 15, ty = tid >> 4;
    const float* Qg = g_Q + (size_t)(b*L_ + lt*64)*D_ + hh*DK_;
    const float* Kg = g_K + (size_t)(b*L_)*D_ + hh*DK_;
    #pragma unroll
    for (int i = 0; i < 4; i++) {
        int idx = tid + i*256;
        int r = idx >> 4, c = (idx & 15) * 4;
        *(float4*)&Qs[r*68 + c] = *(const float4*)&Qg[(size_t)r*D_ + c];
    }
    float maxv[4] = {-3.0e38f, -3.0e38f, -3.0e38f, -3.0e38f};
    for (int mt = 0; mt < 16; mt++) {
        __syncthreads();
        #pragma unroll
        for (int i = 0; i < 4; i++) {
            int idx = tid + i*256;
            int r = idx >> 4, c = (idx & 15) * 4;
            *(float4*)&Ks[r*68 + c] = *(const float4*)&Kg[(size_t)(mt*64 + r)*D_ + c];
        }
        __syncthreads();
        float acc[4][4];
        #pragma unroll
        for (int i = 0; i < 4; i++)
            #pragma unroll
            for (int j = 0; j < 4; j++) acc[i][j] = 0.f;
        #pragma unroll
        for (int k = 0; k < 64; k += 4) {
            float4 q[4], kk[4];
            #pragma unroll
            for (int il = 0; il < 4; il++) q[il]  = *(float4*)&Qs[(il*16+ty)*68 + k];
            #pragma unroll
            for (int im = 0; im < 4; im++) kk[im] = *(float4*)&Ks[(im*16+tx)*68 + k];
            #pragma unroll
            for (int il = 0; il < 4; il++)
                #pragma unroll
                for (int im = 0; im < 4; im++) {
                    acc[il][im] = fmaf(q[il].x, kk[im].x, acc[il][im]);
                    acc[il][im] = fmaf(q[il].y, kk[im].y, acc[il][im]);
                    acc[il][im] = fmaf(q[il].z, kk[im].z, acc[il][im]);
                    acc[il][im] = fmaf(q[il].w, kk[im].w, acc[il][im]);
                }
        }
        #pragma unroll
        for (int il = 0; il < 4; il++)
            #pragma unroll
            for (int im = 0; im < 4; im++)
                maxv[il] = fmaxf(maxv[il], acc[il][im]);
    }
    #pragma unroll
    for (int il = 0; il < 4; il++) red[(il*16+ty)*16 + tx] = maxv[il];
    __syncthreads();
    if (tid < 64) {
        float m = red[tid*16];
        #pragma unroll
        for (int t = 1; t < 16; t++) m = fmaxf(m, red[tid*16 + t]);
        g_rowmax[(b*H_ + hh)*L_ + lt*64 + tid] = m;
    }
}

// ---------------------------------------------------------------------------
// Top-6 per (b,h): 6 sequential argmax passes, tie -> lowest index (= lax.top_k)
// ---------------------------------------------------------------------------
__global__ void __launch_bounds__(256)
topk_kernel() {
    __shared__ float s[1024];
    __shared__ float rv[256];
    __shared__ int   ri[256];
    int bh = blockIdx.x, tid = threadIdx.x;
    #pragma unroll
    for (int i = 0; i < 4; i++) s[tid + i*256] = g_rowmax[bh*L_ + tid + i*256];
    __syncthreads();
    for (int it = 0; it < U_; it++) {
        float v = -3.0e38f; int idx = 1024;
        for (int m = tid; m < 1024; m += 256)
            if (s[m] > v) { v = s[m]; idx = m; }
        rv[tid] = v; ri[tid] = idx; __syncthreads();
        #pragma unroll
        for (int off = 128; off > 0; off >>= 1) {
            if (tid < off) {
                if (rv[tid+off] > rv[tid] ||
                    (rv[tid+off] == rv[tid] && ri[tid+off] < ri[tid])) {
                    rv[tid] = rv[tid+off]; ri[tid] = ri[tid+off];
                }
            }
            __syncthreads();
        }
        if (tid == 0) { g_top[bh*U_ + it] = ri[0]; s[ri[0]] = -3.0e38f; }
        __syncthreads();
    }
}

// ---------------------------------------------------------------------------
// Sparse attention: per (b,h,u) selected row -> softmax over all m -> ctx (64)
// ---------------------------------------------------------------------------
__global__ void __launch_bounds__(256)
ctx_kernel() {
    __shared__ float qs[64];
    __shared__ float s[1024];
    __shared__ float red[256];
    int u = blockIdx.x, hh = blockIdx.y, b = blockIdx.z;
    int tid = threadIdx.x;
    int l = g_top[(b*H_ + hh)*U_ + u];
    if (tid < 16)
        *(float4*)&qs[tid*4] = *(const float4*)&g_Q[(size_t)(b*L_ + l)*D_ + hh*DK_ + tid*4];
    __syncthreads();
    for (int m = tid; m < 1024; m += 256) {
        const float* kr = &g_K[(size_t)(b*L_ + m)*D_ + hh*DK_];
        float acc = 0.f;
        #pragma unroll
        for (int k = 0; k < 64; k += 4) {
            float4 kv = *(const float4*)&kr[k];
            acc = fmaf(qs[k],   kv.x, acc);
            acc = fmaf(qs[k+1], kv.y, acc);
            acc = fmaf(qs[k+2], kv.z, acc);
            acc = fmaf(qs[k+3], kv.w, acc);
        }
        s[m] = acc * 0.125f;
    }
    __syncthreads();
    float v = -3.0e38f;
    for (int m = tid; m < 1024; m += 256) v = fmaxf(v, s[m]);
    float smax = bredMax(v, red);
    float lsum = 0.f;
    for (int m = tid; m < 1024; m += 256) {
        float e = expf(s[m] - smax);
        s[m] = e; lsum += e;
    }
    float ssum = bredSum(lsum, red);
    float inv = 1.0f / ssum;
    int k = tid & 63, g = tid >> 6;
    const float* Vb = &g_V[(size_t)(b*L_)*D_ + hh*DK_ + k];
    float acc = 0.f;
    for (int m = g*256; m < g*256 + 256; m++)
        acc = fmaf(s[m], Vb[(size_t)m*D_], acc);
    red[tid] = acc; __syncthreads();
    if (tid < 64) {
        float c = (red[tid] + red[tid+64] + red[tid+128] + red[tid+192]) * inv;
        g_ctx[((b*H_ + hh)*U_ + u)*DK_ + tid] = c;
    }
}

// ---------------------------------------------------------------------------
// Fused: h = LN( h + bo + sparse(ctx @ Wo_headchunk) ).  1 block / row.
// ---------------------------------------------------------------------------
__global__ void __launch_bounds__(256)
ln1_kernel(const float* __restrict__ Wo, const float* __restrict__ bo,
           const float* __restrict__ g,  const float* __restrict__ bb) {
    __shared__ int   tops[96];
    __shared__ float csh[64];
    __shared__ float red[256];
    int srow = blockIdx.x, b = blockIdx.y, tid = threadIdx.x;
    float4 hv = *(const float4*)&g_h[(size_t)(b*L_ + srow)*D_ + tid*4];
    float4 bo4 = *(const float4*)&bo[tid*4];
    hv.x += bo4.x; hv.y += bo4.y; hv.z += bo4.z; hv.w += bo4.w;
    if (tid < 96) tops[tid] = g_top[b*96 + tid];
    __syncthreads();
    for (int hh = 0; hh < H_; hh++) {
        for (int u = 0; u < U_; u++) {
            if (tops[hh*U_ + u] == srow) {     // uniform branch
                if (tid < 16)
                    *(float4*)&csh[tid*4] =
                        *(const float4*)&g_ctx[((b*H_ + hh)*U_ + u)*DK_ + tid*4];
                __syncthreads();
                #pragma unroll 8
                for (int k = 0; k < 64; k++) {
                    float c = csh[k];
                    float4 w = *(const float4*)&Wo[(size_t)(hh*64 + k)*D_ + tid*4];
                    hv.x = fmaf(c, w.x, hv.x); hv.y = fmaf(c, w.y, hv.y);
                    hv.z = fmaf(c, w.z, hv.z); hv.w = fmaf(c, w.w, hv.w);
                }
                __syncthreads();
            }
        }
    }
    float mean = bredSum(hv.x + hv.y + hv.z + hv.w, red) * (1.0f/1024.0f);
    float cx = hv.x - mean, cy = hv.y - mean, cz = hv.z - mean, cw = hv.w - mean;
    float var = bredSum(cx*cx + cy*cy + cz*cz + cw*cw, red) * (1.0f/1024.0f);
    float rstd = rsqrtf(var + 1e-5f);
    float4 gv = *(const float4*)&g[tid*4];
    float4 bv = *(const float4*)&bb[tid*4];
    float4 o = { cx*rstd*gv.x + bv.x, cy*rstd*gv.y + bv.y,
                 cz*rstd*gv.z + bv.z, cw*rstd*gv.w + bv.w };
    *(float4*)&g_h[(size_t)(b*L_ + srow)*D_ + tid*4] = o;
}

// ---------------------------------------------------------------------------
// Fused FFN + LN2, 4 rows per block.
// ---------------------------------------------------------------------------
__global__ void __launch_bounds__(256)
ffn_kernel(const float* __restrict__ W1, const float* __restrict__ b1,
           const float* __restrict__ W2, const float* __restrict__ b2,
           const float* __restrict__ g,  const float* __restrict__ bb) {
    __shared__ float hs[4][1024];
    __shared__ float pr[256][4];
    __shared__ float tsh[4][32];
    __shared__ float red[256];
    int row0 = blockIdx.x * 4;
    int tid = threadIdx.x;
    #pragma unroll
    for (int r = 0; r < 4; r++)
        *(float4*)&hs[r][tid*4] = *(const float4*)&g_h[(size_t)(row0 + r)*D_ + tid*4];
    __syncthreads();
    int j = tid & 31, grp = tid >> 5;
    float acc[4] = {0.f, 0.f, 0.f, 0.f};
    for (int f = grp*128; f < grp*128 + 128; f++) {
        float w = W1[f*FF_ + j];
        #pragma unroll
        for (int r = 0; r < 4; r++) acc[r] = fmaf(hs[r][f], w, acc[r]);
    }
    #pragma unroll
    for (int r = 0; r < 4; r++) pr[tid][r] = acc[r];
    __syncthreads();
    if (tid < 32) {
        #pragma unroll
        for (int r = 0; r < 4; r++) {
            float t = 0.f;
            #pragma unroll
            for (int gq = 0; gq < 8; gq++) t += pr[gq*32 + tid][r];
            t += b1[tid];
            tsh[r][tid] = fmaxf(t, 0.f);
        }
    }
    __syncthreads();
    float4 y[4];
    #pragma unroll
    for (int r = 0; r < 4; r++) y[r] = *(float4*)&hs[r][tid*4];
    for (int jj = 0; jj < 32; jj++) {
        float4 w2 = *(const float4*)&W2[jj*D_ + tid*4];
        #pragma unroll
        for (int r = 0; r < 4; r++) {
            float t = tsh[r][jj];
            y[r].x = fmaf(t, w2.x, y[r].x); y[r].y = fmaf(t, w2.y, y[r].y);
            y[r].z = fmaf(t, w2.z, y[r].z); y[r].w = fmaf(t, w2.w, y[r].w);
        }
    }
    float4 b2v = *(const float4*)&b2[tid*4];
    float4 gv  = *(const float4*)&g[tid*4];
    float4 bv  = *(const float4*)&bb[tid*4];
    #pragma unroll
    for (int r = 0; r < 4; r++) {
        y[r].x += b2v.x; y[r].y += b2v.y; y[r].z += b2v.z; y[r].w += b2v.w;
        float mean = bredSum(y[r].x + y[r].y + y[r].z + y[r].w, red) * (1.0f/1024.0f);
        float cx = y[r].x - mean, cy = y[r].y - mean, cz = y[r].z - mean, cw = y[r].w - mean;
        float var = bredSum(cx*cx + cy*cy + cz*cz + cw*cw, red) * (1.0f/1024.0f);
        float rstd = rsqrtf(var + 1e-5f);
        float4 o = { cx*rstd*gv.x + bv.x, cy*rstd*gv.y + bv.y,
                     cz*rstd*gv.z + bv.z, cw*rstd*gv.w + bv.w };
        *(float4*)&g_h[(size_t)(row0 + r)*D_ + tid*4] = o;
    }
}

// ---------------------------------------------------------------------------
// Mean over sequence axis, then output projection (1024 -> 96)
// ---------------------------------------------------------------------------
__global__ void mean_kernel() {
    int f = blockIdx.x * 256 + threadIdx.x;
    int b = blockIdx.y;
    float acc = 0.f;
    for (int s = 0; s < L_; s++) acc += g_h[(size_t)(b*L_ + s)*D_ + f];
    g_mean[b*D_ + f] = acc * (1.0f/1024.0f);
}

__global__ void outproj_kernel(const float* __restrict__ outW,
                               const float* __restrict__ outb,
                               float* __restrict__ out) {
    int b = blockIdx.x, j = threadIdx.x;
    if (j < HZN_) {
        float acc = outb[j];
        for (int f = 0; f < D_; f++)
            acc = fmaf(g_mean[b*D_ + f], outW[f*HZN_ + j], acc);
        out[b*HZN_ + j] = acc;
    }
}

// ---------------------------------------------------------------------------
extern "C" void kernel_launch(void* const* d_in, const int* in_sizes, int n_in,
                              void* d_out, int out_size) {
    const float* x     = (const float*)d_in[0];
    const float* emb_W = (const float*)d_in[1];
    const float* emb_b = (const float*)d_in[2];
    const float* Wq    = (const float*)d_in[3];
    const float* bq    = (const float*)d_in[4];
    const float* Wk    = (const float*)d_in[5];
    const float* bk    = (const float*)d_in[6];
    const float* Wv    = (const float*)d_in[7];
    const float* bv    = (const float*)d_in[8];
    const float* Wo    = (const float*)d_in[9];
    const float* bo    = (const float*)d_in[10];
    const float* W1    = (const float*)d_in[11];
    const float* b1    = (const float*)d_in[12];
    const float* W2    = (const float*)d_in[13];
    const float* b2    = (const float*)d_in[14];
    const float* ln1g  = (const float*)d_in[15];
    const float* ln1b  = (const float*)d_in[16];
    const float* ln2g  = (const float*)d_in[17];
    const float* ln2b  = (const float*)d_in[18];
    const float* outW  = (const float*)d_in[19];
    const float* outb  = (const float*)d_in[20];
    float* out = (float*)d_out;

    float *hp, *qp, *kp, *vp;
    cudaGetSymbolAddress((void**)&hp, g_h);
    cudaGetSymbolAddress((void**)&qp, g_Q);
    cudaGetSymbolAddress((void**)&kp, g_K);
    cudaGetSymbolAddress((void**)&vp, g_V);

    embed_kernel<<<dim3(4, 1024, 8), 256>>>(x, emb_W, emb_b);

    for (int layer = 0; layer < 2; layer++) {
        size_t woff = (size_t)layer * D_ * D_;
        size_t boff = (size_t)layer * D_;
        dim3 gg(D_/128, NROWS/128);
        sgemm_bias<<<gg, 256>>>(hp, Wq + woff, bq + boff, qp, NROWS, D_, D_);
        sgemm_bias<<<gg, 256>>>(hp, Wk + woff, bk + boff, kp, NROWS, D_, D_);
        sgemm_bias<<<gg, 256>>>(hp, Wv + woff, bv + boff, vp, NROWS, D_, D_);
        scores_rowmax_kernel<<<dim3(16, 16, 8), 256>>>();
        topk_kernel<<<128, 256>>>();
        ctx_kernel<<<dim3(U_, 16, 8), 256>>>();
        ln1_kernel<<<dim3(1024, 8), 256>>>(Wo + woff, bo + boff,
                                           ln1g + boff, ln1b + boff);
        ffn_kernel<<<NROWS/4, 256>>>(W1 + (size_t)layer*D_*FF_, b1 + (size_t)layer*FF_,
                                     W2 + (size_t)layer*FF_*D_, b2 + boff,
                                     ln2g + boff, ln2b + boff);
    }
    mean_kernel<<<dim3(4, 8), 256>>>();
    outproj_kernel<<<8, 128>>>(outW, outb, out);
}

// round 3
// speedup vs baseline: 1.0717x; 1.0717x over previous
#include <cuda_runtime.h>
#include <cstdint>

// ---------------------------------------------------------------------------
// InformerStandard: B=8, P=16, L=1024, D=1024, H=16(dk=64), HZN=96, FF=32, 2 layers
// Round 3: projection GEMMs via mma.sync tf32x3 (compute_100-compatible).
// ---------------------------------------------------------------------------

#define B_  8
#define L_  1024
#define D_  1024
#define H_  16
#define DK_ 64
#define FF_ 32
#define U_  6
#define HZN_ 96
#define NROWS (B_*L_)   // 8192

__device__ float g_h[B_*L_*D_];       // 32 MB
__device__ float g_Q[B_*L_*D_];
__device__ float g_K[B_*L_*D_];
__device__ float g_V[B_*L_*D_];
__device__ float g_rowmax[B_*H_*L_];
__device__ int   g_top[B_*H_*U_];
__device__ float g_ctx[B_*H_*U_*DK_];
__device__ float g_mean[B_*D_];

#define DI __device__ __forceinline__
#define SWZ(off) ((uint32_t)(off) ^ ((((uint32_t)(off)) >> 3) & 0x70))

DI uint32_t smem_u32(const void* p) {
    uint32_t a;
    asm("{ .reg .u64 t; cvta.to.shared.u64 t, %1; cvt.u32.u64 %0, t; }" : "=r"(a) : "l"(p));
    return a;
}
DI void sts32(uint32_t addr, uint32_t v) {
    asm volatile("st.shared.b32 [%0], %1;" :: "r"(addr), "r"(v) : "memory");
}
DI uint4 lds128(uint32_t addr) {
    uint4 v;
    asm volatile("ld.shared.v4.b32 {%0,%1,%2,%3}, [%4];"
                 : "=r"(v.x), "=r"(v.y), "=r"(v.z), "=r"(v.w) : "r"(addr));
    return v;
}
DI uint32_t tf32_of(float a) {
    uint32_t h;
    asm("cvt.rna.tf32.f32 %0, %1;" : "=r"(h) : "f"(a));
    return h;
}
DI void mma_tf32(float* d, const uint32_t* a, uint32_t b0, uint32_t b1) {
    asm volatile("mma.sync.aligned.m16n8k8.row.col.f32.tf32.tf32.f32 "
                 "{%0,%1,%2,%3}, {%4,%5,%6,%7}, {%8,%9}, {%0,%1,%2,%3};"
                 : "+f"(d[0]), "+f"(d[1]), "+f"(d[2]), "+f"(d[3])
                 : "r"(a[0]), "r"(a[1]), "r"(a[2]), "r"(a[3]), "r"(b0), "r"(b1));
}

// ---------------------------------------------------------------------------
// tf32x3 mma GEMM: C[8192,1024] = A[8192,1024] @ W[1024,1024] + bias.
// CTA tile 128x128, BK=16, 256 threads (8 warps: 4m x 2n), double-buffered.
// Smem holds pre-permuted mma fragments (hi+lo interleaved per lane):
//   A block (kstep,mtile): 32 lanes x 32B (hi 16B | lo 16B), SW128-swizzled.
//   B block (kstep,ntile): 32 lanes x 16B {b0h,b1h,b0l,b1l}.
// ---------------------------------------------------------------------------
#define GEMM_SMEM 65536          // 2 stages x 32KB

DI void gemm_store_chunk(uint32_t sb, int stage, const float4* ra, const float4* rw,
                         int ar, int ac, int bk, int bc) {
    uint32_t sbase = sb + stage * 32768;
    #pragma unroll
    for (int p = 0; p < 2; p++) {
        int r = ar + p * 64;
        int mt = r >> 4, mm = r & 15, g = mm & 7, mh = mm >> 3;
        const float vv[4] = { ra[p].x, ra[p].y, ra[p].z, ra[p].w };
        #pragma unroll
        for (int j = 0; j < 4; j++) {
            int k = ac + j;
            int ks = k >> 3, kk = k & 7, tig = kk & 3, kh = kk >> 2;
            int reg = kh * 2 + mh;
            int ln = g * 4 + tig;
            uint32_t off = ((uint32_t)(ks * 8 + mt) << 10) + SWZ(ln * 32) + reg * 4;
            uint32_t hi = tf32_of(vv[j]);
            uint32_t lo = tf32_of(vv[j] - __uint_as_float(hi));
            sts32(sbase + off, hi);
            sts32(sbase + off + 16, lo);
        }
    }
    {
        int ks = bk >> 3, kk = bk & 7, tig = kk & 3, kh = kk >> 2;
        #pragma unroll
        for (int q = 0; q < 2; q++) {
            const float vv[4] = { rw[q].x, rw[q].y, rw[q].z, rw[q].w };
            #pragma unroll
            for (int j = 0; j < 4; j++) {
                int n = bc + q * 4 + j;
                int nt = n >> 3, g = n & 7;
                int ln = g * 4 + tig;
                uint32_t off = 16384u + ((uint32_t)(ks * 16 + nt) << 9) + ln * 16 + kh * 4;
                uint32_t hi = tf32_of(vv[j]);
                uint32_t lo = tf32_of(vv[j] - __uint_as_float(hi));
                sts32(sbase + off, hi);
                sts32(sbase + off + 8, lo);
            }
        }
    }
}

__global__ void __launch_bounds__(256, 1)
gemm_tc(const float* __restrict__ A, const float* __restrict__ W,
        const float* __restrict__ bias, float* __restrict__ C) {
    extern __shared__ float smf[];
    uint32_t sb = smem_u32(smf);
    int tid = threadIdx.x;
    int wid = tid >> 5, lane = tid & 31;
    int warp_m = wid & 3, warp_n = wid >> 2;
    int n0 = blockIdx.x * 128, m0 = blockIdx.y * 128;
    const float* Ab = A + (size_t)m0 * D_;
    const float* Wb = W + n0;

    int ar = tid >> 2, ac = (tid & 3) * 4;      // A: row, kcol*4
    int bk = tid & 15, bc = (tid >> 4) * 8;     // B: krow, ncol*8

    float acc[2][8][4];
    #pragma unroll
    for (int i = 0; i < 2; i++)
        #pragma unroll
        for (int j = 0; j < 8; j++)
            #pragma unroll
            for (int q = 0; q < 4; q++) acc[i][j][q] = 0.f;

    float4 ra[2], rw[2];
    #pragma unroll
    for (int p = 0; p < 2; p++)
        ra[p] = *(const float4*)(Ab + (size_t)(ar + p * 64) * D_ + ac);
    #pragma unroll
    for (int q = 0; q < 2; q++)
        rw[q] = *(const float4*)(Wb + (size_t)bk * D_ + bc + q * 4);
    gemm_store_chunk(sb, 0, ra, rw, ar, ac, bk, bc);
    __syncthreads();

    uint32_t swzl = SWZ(lane * 32);
    for (int it = 0; it < 64; it++) {
        int cur = it & 1;
        if (it + 1 < 64) {
            int k0 = (it + 1) * 16;
            #pragma unroll
            for (int p = 0; p < 2; p++)
                ra[p] = *(const float4*)(Ab + (size_t)(ar + p * 64) * D_ + k0 + ac);
            #pragma unroll
            for (int q = 0; q < 2; q++)
                rw[q] = *(const float4*)(Wb + (size_t)(k0 + bk) * D_ + bc + q * 4);
        }
        uint32_t stg = sb + cur * 32768;
        #pragma unroll
        for (int ks = 0; ks < 2; ks++) {
            uint32_t ah[2][4], al[2][4];
            #pragma unroll
            for (int mt = 0; mt < 2; mt++) {
                uint32_t ab = stg + ((uint32_t)(ks * 8 + warp_m * 2 + mt) << 10) + swzl;
                uint4 h = lds128(ab);
                uint4 l = lds128(ab + 16);
                ah[mt][0] = h.x; ah[mt][1] = h.y; ah[mt][2] = h.z; ah[mt][3] = h.w;
                al[mt][0] = l.x; al[mt][1] = l.y; al[mt][2] = l.z; al[mt][3] = l.w;
            }
            #pragma unroll
            for (int nt = 0; nt < 8; nt++) {
                uint32_t bbad = stg + 16384u +
                    ((uint32_t)(ks * 16 + warp_n * 8 + nt) << 9) + lane * 16;
                uint4 b = lds128(bbad);
                #pragma unroll
                for (int mt = 0; mt < 2; mt++) {
                    mma_tf32(acc[mt][nt], ah[mt], b.x, b.y);   // Ah*Bh
                    mma_tf32(acc[mt][nt], ah[mt], b.z, b.w);   // Ah*Bl
                    mma_tf32(acc[mt][nt], al[mt], b.x, b.y);   // Al*Bh
                }
            }
        }
        if (it + 1 < 64)
            gemm_store_chunk(sb, cur ^ 1, ra, rw, ar, ac, bk, bc);
        __syncthreads();
    }

    // epilogue
    int g = lane >> 2, tig = lane & 3;
    #pragma unroll
    for (int mt = 0; mt < 2; mt++) {
        int row = m0 + warp_m * 32 + mt * 16 + g;
        #pragma unroll
        for (int nt = 0; nt < 8; nt++) {
            int col = n0 + warp_n * 64 + nt * 8 + tig * 2;
            float b0 = bias[col], b1 = bias[col + 1];
            float2 o0 = { acc[mt][nt][0] + b0, acc[mt][nt][1] + b1 };
            float2 o1 = { acc[mt][nt][2] + b0, acc[mt][nt][3] + b1 };
            *(float2*)(C + (size_t)row * D_ + col) = o0;
            *(float2*)(C + (size_t)(row + 8) * D_ + col) = o1;
        }
    }
}

// ======================= round-1 kernels (unchanged) =======================

DI float bredSum(float v, float* red) {
    int tid = threadIdx.x;
    red[tid] = v; __syncthreads();
    #pragma unroll
    for (int off = 128; off > 0; off >>= 1) {
        if (tid < off) red[tid] += red[tid + off];
        __syncthreads();
    }
    float r = red[0]; __syncthreads(); return r;
}

DI float bredMax(float v, float* red) {
    int tid = threadIdx.x;
    red[tid] = v; __syncthreads();
    #pragma unroll
    for (int off = 128; off > 0; off >>= 1) {
        if (tid < off) red[tid] = fmaxf(red[tid], red[tid + off]);
        __syncthreads();
    }
    float r = red[0]; __syncthreads(); return r;
}

__global__ void embed_kernel(const float* __restrict__ x,
                             const float* __restrict__ emb_W,
                             const float* __restrict__ emb_b) {
    int l = blockIdx.x * 256 + threadIdx.x;
    int d = blockIdx.y;
    int b = blockIdx.z;
    float acc = emb_b[d];
    #pragma unroll
    for (int p = 0; p < 16; p++)
        acc = fmaf(x[(b*16 + p)*L_ + l], emb_W[p*D_ + d], acc);
    const float C = -0.0089944730195f;
    float div = expf((float)(l & ~1) * C);
    float arg = (float)d * div;
    float pe = (l & 1) ? cosf(arg) : sinf(arg);
    g_h[(b*L_ + d)*D_ + l] = acc + pe;
}

__global__ void __launch_bounds__(256)
scores_rowmax_kernel() {
    __shared__ float Qs[64*68];
    __shared__ float Ks[64*68];
    __shared__ float red[64*16];
    int lt = blockIdx.x, hh = blockIdx.y, b = blockIdx.z;
    int tid = threadIdx.x;
    int tx = tid & 15, ty = tid >> 4;
    const float* Qg = g_Q + (size_t)(b*L_ + lt*64)*D_ + hh*DK_;
    const float* Kg = g_K + (size_t)(b*L_)*D_ + hh*DK_;
    #pragma unroll
    for (int i = 0; i < 4; i++) {
        int idx = tid + i*256;
        int r = idx >> 4, c = (idx & 15) * 4;
        *(float4*)&Qs[r*68 + c] = *(const float4*)&Qg[(size_t)r*D_ + c];
    }
    float maxv[4] = {-3.0e38f, -3.0e38f, -3.0e38f, -3.0e38f};
    for (int mt = 0; mt < 16; mt++) {
        __syncthreads();
        #pragma unroll
        for (int i = 0; i < 4; i++) {
            int idx = tid + i*256;
            int r = idx >> 4, c = (idx & 15) * 4;
            *(float4*)&Ks[r*68 + c] = *(const float4*)&Kg[(size_t)(mt*64 + r)*D_ + c];
        }
        __syncthreads();
        float acc[4][4];
        #pragma unroll
        for (int i = 0; i < 4; i++)
            #pragma unroll
            for (int j = 0; j < 4; j++) acc[i][j] = 0.f;
        #pragma unroll
        for (int k = 0; k < 64; k += 4) {
            float4 q[4], kk[4];
            #pragma unroll
            for (int il = 0; il < 4; il++) q[il]  = *(float4*)&Qs[(il*16+ty)*68 + k];
            #pragma unroll
            for (int im = 0; im < 4; im++) kk[im] = *(float4*)&Ks[(im*16+tx)*68 + k];
            #pragma unroll
            for (int il = 0; il < 4; il++)
                #pragma unroll
                for (int im = 0; im < 4; im++) {
                    acc[il][im] = fmaf(q[il].x, kk[im].x, acc[il][im]);
                    acc[il][im] = fmaf(q[il].y, kk[im].y, acc[il][im]);
                    acc[il][im] = fmaf(q[il].z, kk[im].z, acc[il][im]);
                    acc[il][im] = fmaf(q[il].w, kk[im].w, acc[il][im]);
                }
        }
        #pragma unroll
        for (int il = 0; il < 4; il++)
            #pragma unroll
            for (int im = 0; im < 4; im++)
                maxv[il] = fmaxf(maxv[il], acc[il][im]);
    }
    #pragma unroll
    for (int il = 0; il < 4; il++) red[(il*16+ty)*16 + tx] = maxv[il];
    __syncthreads();
    if (tid < 64) {
        float m = red[tid*16];
        #pragma unroll
        for (int t = 1; t < 16; t++) m = fmaxf(m, red[tid*16 + t]);
        g_rowmax[(b*H_ + hh)*L_ + lt*64 + tid] = m;
    }
}

__global__ void __launch_bounds__(256)
topk_kernel() {
    __shared__ float s[1024];
    __shared__ float rv[256];
    __shared__ int   ri[256];
    int bh = blockIdx.x, tid = threadIdx.x;
    #pragma unroll
    for (int i = 0; i < 4; i++) s[tid + i*256] = g_rowmax[bh*L_ + tid + i*256];
    __syncthreads();
    for (int it = 0; it < U_; it++) {
        float v = -3.0e38f; int idx = 1024;
        for (int m = tid; m < 1024; m += 256)
            if (s[m] > v) { v = s[m]; idx = m; }
        rv[tid] = v; ri[tid] = idx; __syncthreads();
        #pragma unroll
        for (int off = 128; off > 0; off >>= 1) {
            if (tid < off) {
                if (rv[tid+off] > rv[tid] ||
                    (rv[tid+off] == rv[tid] && ri[tid+off] < ri[tid])) {
                    rv[tid] = rv[tid+off]; ri[tid] = ri[tid+off];
                }
            }
            __syncthreads();
        }
        if (tid == 0) { g_top[bh*U_ + it] = ri[0]; s[ri[0]] = -3.0e38f; }
        __syncthreads();
    }
}

__global__ void __launch_bounds__(256)
ctx_kernel() {
    __shared__ float qs[64];
    __shared__ float s[1024];
    __shared__ float red[256];
    int u = blockIdx.x, hh = blockIdx.y, b = blockIdx.z;
    int tid = threadIdx.x;
    int l = g_top[(b*H_ + hh)*U_ + u];
    if (tid < 16)
        *(float4*)&qs[tid*4] = *(const float4*)&g_Q[(size_t)(b*L_ + l)*D_ + hh*DK_ + tid*4];
    __syncthreads();
    for (int m = tid; m < 1024; m += 256) {
        const float* kr = &g_K[(size_t)(b*L_ + m)*D_ + hh*DK_];
        float acc = 0.f;
        #pragma unroll
        for (int k = 0; k < 64; k += 4) {
            float4 kv = *(const float4*)&kr[k];
            acc = fmaf(qs[k],   kv.x, acc);
            acc = fmaf(qs[k+1], kv.y, acc);
            acc = fmaf(qs[k+2], kv.z, acc);
            acc = fmaf(qs[k+3], kv.w, acc);
        }
        s[m] = acc * 0.125f;
    }
    __syncthreads();
    float v = -3.0e38f;
    for (int m = tid; m < 1024; m += 256) v = fmaxf(v, s[m]);
    float smax = bredMax(v, red);
    float lsum = 0.f;
    for (int m = tid; m < 1024; m += 256) {
        float e = expf(s[m] - smax);
        s[m] = e; lsum += e;
    }
    float ssum = bredSum(lsum, red);
    float inv = 1.0f / ssum;
    int k = tid & 63, g = tid >> 6;
    const float* Vb = &g_V[(size_t)(b*L_)*D_ + hh*DK_ + k];
    float acc = 0.f;
    for (int m = g*256; m < g*256 + 256; m++)
        acc = fmaf(s[m], Vb[(size_t)m*D_], acc);
    red[tid] = acc; __syncthreads();
    if (tid < 64) {
        float c = (red[tid] + red[tid+64] + red[tid+128] + red[tid+192]) * inv;
        g_ctx[((b*H_ + hh)*U_ + u)*DK_ + tid] = c;
    }
}

__global__ void __launch_bounds__(256)
ln1_kernel(const float* __restrict__ Wo, const float* __restrict__ bo,
           const float* __restrict__ g,  const float* __restrict__ bb) {
    __shared__ int   tops[96];
    __shared__ float csh[64];
    __shared__ float red[256];
    int srow = blockIdx.x, b = blockIdx.y, tid = threadIdx.x;
    float4 hv = *(const float4*)&g_h[(size_t)(b*L_ + srow)*D_ + tid*4];
    float4 bo4 = *(const float4*)&bo[tid*4];
    hv.x += bo4.x; hv.y += bo4.y; hv.z += bo4.z; hv.w += bo4.w;
    if (tid < 96) tops[tid] = g_top[b*96 + tid];
    __syncthreads();
    for (int hh = 0; hh < H_; hh++) {
        for (int u = 0; u < U_; u++) {
            if (tops[hh*U_ + u] == srow) {
                if (tid < 16)
                    *(float4*)&csh[tid*4] =
                        *(const float4*)&g_ctx[((b*H_ + hh)*U_ + u)*DK_ + tid*4];
                __syncthreads();
                #pragma unroll 8
                for (int k = 0; k < 64; k++) {
                    float c = csh[k];
                    float4 w = *(const float4*)&Wo[(size_t)(hh*64 + k)*D_ + tid*4];
                    hv.x = fmaf(c, w.x, hv.x); hv.y = fmaf(c, w.y, hv.y);
                    hv.z = fmaf(c, w.z, hv.z); hv.w = fmaf(c, w.w, hv.w);
                }
                __syncthreads();
            }
        }
    }
    float mean = bredSum(hv.x + hv.y + hv.z + hv.w, red) * (1.0f/1024.0f);
    float cx = hv.x - mean, cy = hv.y - mean, cz = hv.z - mean, cw = hv.w - mean;
    float var = bredSum(cx*cx + cy*cy + cz*cz + cw*cw, red) * (1.0f/1024.0f);
    float rstd = rsqrtf(var + 1e-5f);
    float4 gv = *(const float4*)&g[tid*4];
    float4 bv = *(const float4*)&bb[tid*4];
    float4 o = { cx*rstd*gv.x + bv.x, cy*rstd*gv.y + bv.y,
                 cz*rstd*gv.z + bv.z, cw*rstd*gv.w + bv.w };
    *(float4*)&g_h[(size_t)(b*L_ + srow)*D_ + tid*4] = o;
}

__global__ void __launch_bounds__(256)
ffn_kernel(const float* __restrict__ W1, const float* __restrict__ b1,
           const float* __restrict__ W2, const float* __restrict__ b2,
           const float* __restrict__ g,  const float* __restrict__ bb) {
    __shared__ float hs[4][1024];
    __shared__ float pr[256][4];
    __shared__ float tsh[4][32];
    __shared__ float red[256];
    int row0 = blockIdx.x * 4;
    int tid = threadIdx.x;
    #pragma unroll
    for (int r = 0; r < 4; r++)
        *(float4*)&hs[r][tid*4] = *(const float4*)&g_h[(size_t)(row0 + r)*D_ + tid*4];
    __syncthreads();
    int j = tid & 31, grp = tid >> 5;
    float acc[4] = {0.f, 0.f, 0.f, 0.f};
    for (int f = grp*128; f < grp*128 + 128; f++) {
        float w = W1[f*FF_ + j];
        #pragma unroll
        for (int r = 0; r < 4; r++) acc[r] = fmaf(hs[r][f], w, acc[r]);
    }
    #pragma unroll
    for (int r = 0; r < 4; r++) pr[tid][r] = acc[r];
    __syncthreads();
    if (tid < 32) {
        #pragma unroll
        for (int r = 0; r < 4; r++) {
            float t = 0.f;
            #pragma unroll
            for (int gq = 0; gq < 8; gq++) t += pr[gq*32 + tid][r];
            t += b1[tid];
            tsh[r][tid] = fmaxf(t, 0.f);
        }
    }
    __syncthreads();
    float4 y[4];
    #pragma unroll
    for (int r = 0; r < 4; r++) y[r] = *(float4*)&hs[r][tid*4];
    for (int jj = 0; jj < 32; jj++) {
        float4 w2 = *(const float4*)&W2[jj*D_ + tid*4];
        #pragma unroll
        for (int r = 0; r < 4; r++) {
            float t = tsh[r][jj];
            y[r].x = fmaf(t, w2.x, y[r].x); y[r].y = fmaf(t, w2.y, y[r].y);
            y[r].z = fmaf(t, w2.z, y[r].z); y[r].w = fmaf(t, w2.w, y[r].w);
        }
    }
    float4 b2v = *(const float4*)&b2[tid*4];
    float4 gv  = *(const float4*)&g[tid*4];
    float4 bv  = *(const float4*)&bb[tid*4];
    #pragma unroll
    for (int r = 0; r < 4; r++) {
        y[r].x += b2v.x; y[r].y += b2v.y; y[r].z += b2v.z; y[r].w += b2v.w;
        float mean = bredSum(y[r].x + y[r].y + y[r].z + y[r].w, red) * (1.0f/1024.0f);
        float cx = y[r].x - mean, cy = y[r].y - mean, cz = y[r].z - mean, cw = y[r].w - mean;
        float var = bredSum(cx*cx + cy*cy + cz*cz + cw*cw, red) * (1.0f/1024.0f);
        float rstd = rsqrtf(var + 1e-5f);
        float4 o = { cx*rstd*gv.x + bv.x, cy*rstd*gv.y + bv.y,
                     cz*rstd*gv.z + bv.z, cw*rstd*gv.w + bv.w };
        *(float4*)&g_h[(size_t)(row0 + r)*D_ + tid*4] = o;
    }
}

__global__ void mean_kernel() {
    int f = blockIdx.x * 256 + threadIdx.x;
    int b = blockIdx.y;
    float acc = 0.f;
    for (int s = 0; s < L_; s++) acc += g_h[(size_t)(b*L_ + s)*D_ + f];
    g_mean[b*D_ + f] = acc * (1.0f/1024.0f);
}

__global__ void outproj_kernel(const float* __restrict__ outW,
                               const float* __restrict__ outb,
                               float* __restrict__ out) {
    int b = blockIdx.x, j = threadIdx.x;
    if (j < HZN_) {
        float acc = outb[j];
        for (int f = 0; f < D_; f++)
            acc = fmaf(g_mean[b*D_ + f], outW[f*HZN_ + j], acc);
        out[b*HZN_ + j] = acc;
    }
}

// ---------------------------------------------------------------------------
extern "C" void kernel_launch(void* const* d_in, const int* in_sizes, int n_in,
                              void* d_out, int out_size) {
    const float* x     = (const float*)d_in[0];
    const float* emb_W = (const float*)d_in[1];
    const float* emb_b = (const float*)d_in[2];
    const float* Wq    = (const float*)d_in[3];
    const float* bq    = (const float*)d_in[4];
    const float* Wk    = (const float*)d_in[5];
    const float* bk    = (const float*)d_in[6];
    const float* Wv    = (const float*)d_in[7];
    const float* bv    = (const float*)d_in[8];
    const float* Wo    = (const float*)d_in[9];
    const float* bo    = (const float*)d_in[10];
    const float* W1    = (const float*)d_in[11];
    const float* b1    = (const float*)d_in[12];
    const float* W2    = (const float*)d_in[13];
    const float* b2    = (const float*)d_in[14];
    const float* ln1g  = (const float*)d_in[15];
    const float* ln1b  = (const float*)d_in[16];
    const float* ln2g  = (const float*)d_in[17];
    const float* ln2b  = (const float*)d_in[18];
    const float* outW  = (const float*)d_in[19];
    const float* outb  = (const float*)d_in[20];
    float* out = (float*)d_out;

    float *hp, *qp, *kp, *vp;
    cudaGetSymbolAddress((void**)&hp, g_h);
    cudaGetSymbolAddress((void**)&qp, g_Q);
    cudaGetSymbolAddress((void**)&kp, g_K);
    cudaGetSymbolAddress((void**)&vp, g_V);

    cudaFuncSetAttribute(gemm_tc, cudaFuncAttributeMaxDynamicSharedMemorySize, GEMM_SMEM);

    embed_kernel<<<dim3(4, 1024, 8), 256>>>(x, emb_W, emb_b);

    for (int layer = 0; layer < 2; layer++) {
        size_t woff = (size_t)layer * D_ * D_;
        size_t boff = (size_t)layer * D_;
        dim3 gg(D_/128, NROWS/128);
        gemm_tc<<<gg, 256, GEMM_SMEM>>>(hp, Wq + woff, bq + boff, qp);
        gemm_tc<<<gg, 256, GEMM_SMEM>>>(hp, Wk + woff, bk + boff, kp);
        gemm_tc<<<gg, 256, GEMM_SMEM>>>(hp, Wv + woff, bv + boff, vp);
        scores_rowmax_kernel<<<dim3(16, 16, 8), 256>>>();
        topk_kernel<<<128, 256>>>();
        ctx_kernel<<<dim3(U_, 16, 8), 256>>>();
        ln1_kernel<<<dim3(1024, 8), 256>>>(Wo + woff, bo + boff,
                                           ln1g + boff, ln1b + boff);
        ffn_kernel<<<NROWS/4, 256>>>(W1 + (size_t)layer*D_*FF_, b1 + (size_t)layer*FF_,
                                     W2 + (size_t)layer*FF_*D_, b2 + boff,
                                     ln2g + boff, ln2b + boff);
    }
    mean_kernel<<<dim3(4, 8), 256>>>();
    outproj_kernel<<<8, 128>>>(outW, outb, out);
}